// round 11
// baseline (speedup 1.0000x reference)
#include <cuda_runtime.h>
#include <cstdint>

#define MAX_NODES 100000
#define MAX_EDGES 1600000
#define SCAN_BLK 1024
#define NCHUNK 4

typedef unsigned long long u64;

// Scratch (allocation-free device globals); 256B-aligned for float4 access.
__device__ __align__(256) float g_h[(size_t)MAX_NODES * 128];   // h1 = X@W1
__device__ __align__(256) float g_y[(size_t)MAX_NODES * 128];   // layer-1 output
__device__ __align__(256) float g_h2[(size_t)MAX_NODES * 64];   // h2 = y@W2
__device__ __align__(256) float g_dinv[MAX_NODES];
__device__ __align__(256) int   g_degi[MAX_NODES];
__device__ __align__(256) int   g_rtmp[MAX_NODES];
__device__ __align__(256) int   g_row_ptr[MAX_NODES + 1];
__device__ __align__(256) int   g_cursor[MAX_NODES];
__device__ __align__(256) int   g_csr_src[MAX_EDGES];
__device__ __align__(256) int   g_bsums[(MAX_NODES + SCAN_BLK - 1) / SCAN_BLK + 1];
__device__ int g_i64;   // 1 if edge_index is int64, 0 if int32

// ---------------------------------------------------------------------------
// Edge dtype detection (1 warp): int64 values < 1e5 have all-zero high words.
// ---------------------------------------------------------------------------
__global__ void detect_dtype_kernel(const int* __restrict__ ei32, int n_elem) {
    int lim = n_elem < 2048 ? n_elem : 2048;
    int acc = 0;
    for (int i = 1 + 2 * threadIdx.x; i < lim; i += 64) acc |= ei32[i];
    acc = __reduce_or_sync(0xffffffffu, acc);
    if (threadIdx.x == 0) g_i64 = (acc == 0) ? 1 : 0;
}

__device__ __forceinline__ int edge_val(const int* __restrict__ ei32, size_t elem, int sh) {
    return ei32[elem << sh];
}

// ---------------------------------------------------------------------------
// CSR build: degree histogram -> exclusive scan -> cursor fill
// ---------------------------------------------------------------------------
__global__ void count_deg_kernel(const int* __restrict__ ei32, int E, int M) {
    int e = blockIdx.x * blockDim.x + threadIdx.x;
    if (e < E) {
        int sh = g_i64;
        int d = edge_val(ei32, (size_t)E + e, sh);
        if ((unsigned)d < (unsigned)M) atomicAdd(&g_degi[d], 1);
    }
}

__global__ void dinv_kernel(int M) {
    int i = blockIdx.x * blockDim.x + threadIdx.x;
    if (i < M) g_dinv[i] = rsqrtf((float)g_degi[i] + 1.0f);  // +1 self loop
}

__global__ void scan1_kernel(int M) {
    __shared__ int sm[SCAN_BLK];
    int i = blockIdx.x * SCAN_BLK + threadIdx.x;
    int v = (i < M) ? g_degi[i] : 0;
    sm[threadIdx.x] = v;
    __syncthreads();
    for (int off = 1; off < SCAN_BLK; off <<= 1) {
        int t = (threadIdx.x >= off) ? sm[threadIdx.x - off] : 0;
        __syncthreads();
        sm[threadIdx.x] += t;
        __syncthreads();
    }
    if (i < M) g_rtmp[i] = sm[threadIdx.x] - v;          // exclusive within block
    if (threadIdx.x == SCAN_BLK - 1) g_bsums[blockIdx.x] = sm[SCAN_BLK - 1];
}

__global__ void scan2_kernel(int nb) {       // nb <= 128: one-block Hillis-Steele
    __shared__ int sm[128];
    int t = threadIdx.x;
    int v = (t < nb) ? g_bsums[t] : 0;
    sm[t] = v;
    __syncthreads();
    for (int off = 1; off < 128; off <<= 1) {
        int u = (t >= off) ? sm[t - off] : 0;
        __syncthreads();
        sm[t] += u;
        __syncthreads();
    }
    if (t < nb) g_bsums[t] = sm[t] - v;      // exclusive
}

__global__ void scan3_kernel(int M) {
    int i = blockIdx.x * blockDim.x + threadIdx.x;
    if (i < M) {
        int rp = g_rtmp[i] + g_bsums[i / SCAN_BLK];
        g_row_ptr[i] = rp;
        g_cursor[i]  = rp;
        if (i == M - 1) g_row_ptr[M] = rp + g_degi[i];
    }
}

__global__ void fill_csr_kernel(const int* __restrict__ ei32, int E, int M) {
    int e = blockIdx.x * blockDim.x + threadIdx.x;
    if (e < E) {
        int sh = g_i64;
        int s = edge_val(ei32, (size_t)e, sh);
        int d = edge_val(ei32, (size_t)E + e, sh);
        if ((unsigned)s < (unsigned)M && (unsigned)d < (unsigned)M) {
            int pos = atomicAdd(&g_cursor[d], 1);
            g_csr_src[pos] = s;
        }
    }
}

// ---------------------------------------------------------------------------
// fma.rn.f32x2 helper (even/odd-K packed partial sums)
// ---------------------------------------------------------------------------
__device__ __forceinline__ void fma2(u64& d, u64 a, u64 b) {
    asm("fma.rn.f32x2 %0, %1, %2, %0;" : "+l"(d) : "l"(a), "l"(b));
}

// ---------------------------------------------------------------------------
// GEMM: H[M,NC] = X[M,128] @ W[128,NC] with packed f32x2 (K-pair partial sums)
// ---------------------------------------------------------------------------
template <int NC>
__global__ void __launch_bounds__(256) gemm_kernel(
        const float* __restrict__ X, const float* __restrict__ W,
        float* __restrict__ H, int M) {
    constexpr int WSTRIDE = 130;
    extern __shared__ float sh[];
    float* shWt = sh;                      // NC * WSTRIDE floats (transposed W)
    float* shX  = sh + NC * WSTRIDE;       // ROWS * 128 floats
    constexpr int ROWS = (NC == 128) ? 64 : 128;

    const int tid = threadIdx.x;
    const int rowBase = blockIdx.x * ROWS;

    for (int i = tid; i < 128 * NC; i += 256) {
        int k = i / NC, c = i % NC;
        shWt[c * WSTRIDE + k] = W[i];
    }
    for (int i = tid; i < ROWS * 32; i += 256) {
        int r = i >> 5;
        int gr = rowBase + r;
        float4 v = make_float4(0.f, 0.f, 0.f, 0.f);
        if (gr < M) v = ((const float4*)X)[(size_t)gr * 32 + (i & 31)];
        ((float4*)shX)[i] = v;
    }
    __syncthreads();

    const int warp = tid >> 5, lane = tid & 31;
    constexpr int CGRP = (NC == 128) ? 32 : 16;
    const int lc  = lane % CGRP;
    const int grp = lane / CGRP;
    constexpr int RPW = ROWS / 8;
    const int r0 = warp * RPW + grp * 8;

    u64 acc[8][4];
    #pragma unroll
    for (int r = 0; r < 8; ++r)
        #pragma unroll
        for (int j = 0; j < 4; ++j) acc[r][j] = 0ULL;

    const float* wbase = &shWt[lc * WSTRIDE];

    #pragma unroll 4
    for (int k2 = 0; k2 < 64; ++k2) {
        u64 w2[4];
        #pragma unroll
        for (int j = 0; j < 4; ++j)
            w2[j] = *(const u64*)&wbase[j * (CGRP * WSTRIDE) + 2 * k2];
        #pragma unroll
        for (int r = 0; r < 8; ++r) {
            u64 x2 = *(const u64*)&shX[(r0 + r) * 128 + 2 * k2];
            fma2(acc[r][0], x2, w2[0]);
            fma2(acc[r][1], x2, w2[1]);
            fma2(acc[r][2], x2, w2[2]);
            fma2(acc[r][3], x2, w2[3]);
        }
    }

    #pragma unroll
    for (int r = 0; r < 8; ++r) {
        int gr = rowBase + r0 + r;
        if (gr < M) {
            #pragma unroll
            for (int j = 0; j < 4; ++j) {
                u64 a = acc[r][j];
                float lo = __uint_as_float((unsigned)(a & 0xffffffffULL));
                float hi = __uint_as_float((unsigned)(a >> 32));
                H[(size_t)gr * NC + lc + CGRP * j] = lo + hi;
            }
        }
    }
}

// ---------------------------------------------------------------------------
// Gather (CSR): out[d] = [relu]( dinv[d]*(h[d]*dinv[d] + sum_s h[s]*dinv[s]) + b )
// row0/nrows: chunk support (row = row0 + warp-id within launch).
// ---------------------------------------------------------------------------
template <bool RELU>
__global__ void gather128_kernel(const float* __restrict__ Hs, const float* __restrict__ b,
                                 float* __restrict__ out, int row0, int nrows) {
    int lr = (blockIdx.x * blockDim.x + threadIdx.x) >> 5;
    int lane = threadIdx.x & 31;
    if (lr >= nrows) return;
    int row = row0 + lr;
    int p0 = __ldg(&g_row_ptr[row]);
    int p1 = __ldg(&g_row_ptr[row + 1]);
    float di = __ldg(&g_dinv[row]);
    float4 acc = __ldg((const float4*)&Hs[(size_t)row * 128 + lane * 4]);   // self loop
    acc.x *= di; acc.y *= di; acc.z *= di; acc.w *= di;
    for (int base = p0; base < p1; base += 32) {
        int pl = base + lane;
        int s_l = 0; float dl = 0.f;
        if (pl < p1) { s_l = __ldg(&g_csr_src[pl]); dl = __ldg(&g_dinv[s_l]); }
        int n = min(32, p1 - base);
        int k = 0;
        for (; k + 4 <= n; k += 4) {
            int s0 = __shfl_sync(0xffffffffu, s_l, k);
            int s1 = __shfl_sync(0xffffffffu, s_l, k + 1);
            int s2 = __shfl_sync(0xffffffffu, s_l, k + 2);
            int s3 = __shfl_sync(0xffffffffu, s_l, k + 3);
            float d0 = __shfl_sync(0xffffffffu, dl, k);
            float d1 = __shfl_sync(0xffffffffu, dl, k + 1);
            float d2 = __shfl_sync(0xffffffffu, dl, k + 2);
            float d3 = __shfl_sync(0xffffffffu, dl, k + 3);
            float4 v0 = __ldg((const float4*)&Hs[(size_t)s0 * 128 + lane * 4]);
            float4 v1 = __ldg((const float4*)&Hs[(size_t)s1 * 128 + lane * 4]);
            float4 v2 = __ldg((const float4*)&Hs[(size_t)s2 * 128 + lane * 4]);
            float4 v3 = __ldg((const float4*)&Hs[(size_t)s3 * 128 + lane * 4]);
            acc.x += v0.x * d0 + v1.x * d1 + v2.x * d2 + v3.x * d3;
            acc.y += v0.y * d0 + v1.y * d1 + v2.y * d2 + v3.y * d3;
            acc.z += v0.z * d0 + v1.z * d1 + v2.z * d2 + v3.z * d3;
            acc.w += v0.w * d0 + v1.w * d1 + v2.w * d2 + v3.w * d3;
        }
        for (; k < n; ++k) {
            int s = __shfl_sync(0xffffffffu, s_l, k);
            float d = __shfl_sync(0xffffffffu, dl, k);
            float4 v = __ldg((const float4*)&Hs[(size_t)s * 128 + lane * 4]);
            acc.x += v.x * d; acc.y += v.y * d; acc.z += v.z * d; acc.w += v.w * d;
        }
    }
    float4 bv = __ldg((const float4*)&b[lane * 4]);
    float4 o;
    o.x = acc.x * di + bv.x;
    o.y = acc.y * di + bv.y;
    o.z = acc.z * di + bv.z;
    o.w = acc.w * di + bv.w;
    if (RELU) {
        o.x = fmaxf(o.x, 0.f); o.y = fmaxf(o.y, 0.f);
        o.z = fmaxf(o.z, 0.f); o.w = fmaxf(o.w, 0.f);
    }
    *(float4*)&out[(size_t)row * 128 + lane * 4] = o;
}

__global__ void gather64_kernel(const float* __restrict__ Hs, const float* __restrict__ b,
                                float* __restrict__ out, int M) {
    int row = (blockIdx.x * blockDim.x + threadIdx.x) >> 5;
    int lane = threadIdx.x & 31;
    if (row >= M) return;
    int p0 = __ldg(&g_row_ptr[row]);
    int p1 = __ldg(&g_row_ptr[row + 1]);
    float di = __ldg(&g_dinv[row]);
    float2 acc = __ldg((const float2*)&Hs[(size_t)row * 64 + lane * 2]);    // self loop
    acc.x *= di; acc.y *= di;
    for (int base = p0; base < p1; base += 32) {
        int pl = base + lane;
        int s_l = 0; float dl = 0.f;
        if (pl < p1) { s_l = __ldg(&g_csr_src[pl]); dl = __ldg(&g_dinv[s_l]); }
        int n = min(32, p1 - base);
        int k = 0;
        for (; k + 4 <= n; k += 4) {
            int s0 = __shfl_sync(0xffffffffu, s_l, k);
            int s1 = __shfl_sync(0xffffffffu, s_l, k + 1);
            int s2 = __shfl_sync(0xffffffffu, s_l, k + 2);
            int s3 = __shfl_sync(0xffffffffu, s_l, k + 3);
            float d0 = __shfl_sync(0xffffffffu, dl, k);
            float d1 = __shfl_sync(0xffffffffu, dl, k + 1);
            float d2 = __shfl_sync(0xffffffffu, dl, k + 2);
            float d3 = __shfl_sync(0xffffffffu, dl, k + 3);
            float2 v0 = __ldg((const float2*)&Hs[(size_t)s0 * 64 + lane * 2]);
            float2 v1 = __ldg((const float2*)&Hs[(size_t)s1 * 64 + lane * 2]);
            float2 v2 = __ldg((const float2*)&Hs[(size_t)s2 * 64 + lane * 2]);
            float2 v3 = __ldg((const float2*)&Hs[(size_t)s3 * 64 + lane * 2]);
            acc.x += v0.x * d0 + v1.x * d1 + v2.x * d2 + v3.x * d3;
            acc.y += v0.y * d0 + v1.y * d1 + v2.y * d2 + v3.y * d3;
        }
        for (; k < n; ++k) {
            int s = __shfl_sync(0xffffffffu, s_l, k);
            float d = __shfl_sync(0xffffffffu, dl, k);
            float2 v = __ldg((const float2*)&Hs[(size_t)s * 64 + lane * 2]);
            acc.x += v.x * d; acc.y += v.y * d;
        }
    }
    float2 bv = __ldg((const float2*)&b[lane * 2]);
    float2 o;
    o.x = acc.x * di + bv.x;
    o.y = acc.y * di + bv.y;
    *(float2*)&out[(size_t)row * 64 + lane * 2] = o;
}

// ---------------------------------------------------------------------------
// Launch — CSR chain overlapped with gemm128; gather128/gemm64 chunk-pipelined
// across two streams (gather = LTS pipe, gemm = FMA pipe).
// ---------------------------------------------------------------------------
extern "C" void kernel_launch(void* const* d_in, const int* in_sizes, int n_in,
                              void* d_out, int out_size) {
    int idxs[8];
    for (int i = 0; i < n_in; ++i) idxs[i] = i;
    for (int i = 0; i < n_in; ++i)
        for (int j = i + 1; j < n_in; ++j)
            if (in_sizes[idxs[j]] > in_sizes[idxs[i]]) { int t = idxs[i]; idxs[i] = idxs[j]; idxs[j] = t; }

    const float* x    = (const float*)d_in[idxs[0]];
    const int*   ei32 = (const int*)  d_in[idxs[1]];
    const float* W1   = (const float*)d_in[idxs[2]];
    const float* W2   = (const float*)d_in[idxs[3]];
    const float* b1   = (const float*)d_in[idxs[4]];
    const float* b2   = (const float*)d_in[idxs[5]];
    const int x_elems = in_sizes[idxs[0]];
    const int e_elems = in_sizes[idxs[1]];

    const int M = x_elems / 128;   // 100000
    const int E = e_elems / 2;     // 1600000
    const int NB = (M + SCAN_BLK - 1) / SCAN_BLK;

    void *p_degi, *p_h, *p_y, *p_h2;
    cudaGetSymbolAddress(&p_degi, g_degi);
    cudaGetSymbolAddress(&p_h,    g_h);
    cudaGetSymbolAddress(&p_y,    g_y);
    cudaGetSymbolAddress(&p_h2,   g_h2);

    const int SMEM128 = (128 * 130 + 64 * 128) * 4;   // 99,328 B
    const int SMEM64  = (64 * 130 + 128 * 128) * 4;   // 98,816 B
    cudaFuncSetAttribute(gemm_kernel<128>, cudaFuncAttributeMaxDynamicSharedMemorySize, SMEM128);
    cudaFuncSetAttribute(gemm_kernel<64>,  cudaFuncAttributeMaxDynamicSharedMemorySize, SMEM64);

    static cudaStream_t sB = nullptr;
    static cudaEvent_t evF = nullptr, evJ = nullptr, evG2 = nullptr;
    static cudaEvent_t evC[NCHUNK];
    if (!sB) {
        cudaStreamCreateWithFlags(&sB, cudaStreamNonBlocking);
        cudaEventCreateWithFlags(&evF, cudaEventDisableTiming);
        cudaEventCreateWithFlags(&evJ, cudaEventDisableTiming);
        cudaEventCreateWithFlags(&evG2, cudaEventDisableTiming);
        for (int c = 0; c < NCHUNK; ++c)
            cudaEventCreateWithFlags(&evC[c], cudaEventDisableTiming);
    }

    // Fork: CSR chain on side stream sB (overlaps gemm128).
    cudaEventRecord(evF, 0);
    cudaStreamWaitEvent(sB, evF, 0);
    detect_dtype_kernel<<<1, 32, 0, sB>>>(ei32, e_elems);
    cudaMemsetAsync(p_degi, 0, (size_t)M * sizeof(int), sB);
    count_deg_kernel<<<(E + 255) / 256, 256, 0, sB>>>(ei32, E, M);
    dinv_kernel<<<(M + 255) / 256, 256, 0, sB>>>(M);
    scan1_kernel<<<NB, SCAN_BLK, 0, sB>>>(M);
    scan2_kernel<<<1, 128, 0, sB>>>(NB);
    scan3_kernel<<<(M + 255) / 256, 256, 0, sB>>>(M);
    fill_csr_kernel<<<(E + 255) / 256, 256, 0, sB>>>(ei32, E, M);
    cudaEventRecord(evJ, sB);

    // Concurrent: layer-1 GEMM (depends only on x, W1).
    gemm_kernel<128><<<(M + 63) / 64, 256, SMEM128>>>(x, W1, (float*)p_h, M);

    // Join CSR, then chunk-pipelined gather128 (main) + gemm64 (side).
    cudaStreamWaitEvent(0, evJ, 0);

    // Chunk size: multiple of 128 rows (gemm64 block granularity).
    int chunk = ((M + NCHUNK - 1) / NCHUNK + 127) & ~127;
    for (int c = 0; c < NCHUNK; ++c) {
        int row0 = c * chunk;
        if (row0 >= M) { cudaEventRecord(evC[c], 0); continue; }
        int nrows = (row0 + chunk <= M) ? chunk : (M - row0);
        gather128_kernel<true><<<(nrows * 32 + 255) / 256, 256>>>(
            (const float*)p_h, b1, (float*)p_y, row0, nrows);
        cudaEventRecord(evC[c], 0);
        cudaStreamWaitEvent(sB, evC[c], 0);
        gemm_kernel<64><<<(nrows + 127) / 128, 256, SMEM64, sB>>>(
            (const float*)p_y + (size_t)row0 * 128, W2,
            (float*)p_h2 + (size_t)row0 * 64, nrows);
    }
    cudaEventRecord(evG2, sB);
    cudaStreamWaitEvent(0, evG2, 0);

    gather64_kernel<<<(M * 32 + 255) / 256, 256>>>(
        (const float*)p_h2, b2, (float*)d_out, M);
}

// round 12
// speedup vs baseline: 1.4841x; 1.4841x over previous
#include <cuda_runtime.h>
#include <cuda_fp16.h>
#include <cstdint>

#define MAX_NODES 100000
#define MAX_EDGES 1600000
#define SCAN_BLK 1024

typedef unsigned long long u64;

// Scratch (allocation-free device globals); 256B-aligned.
__device__ __align__(256) __half g_h1h[(size_t)MAX_NODES * 128]; // h1 = X@W1 (fp16)
__device__ __align__(256) float  g_y[(size_t)MAX_NODES * 128];   // layer-1 output (fp32)
__device__ __align__(256) __half g_h2h[(size_t)MAX_NODES * 64];  // h2 = y@W2 (fp16)
__device__ __align__(256) float  g_dinv[MAX_NODES];
__device__ __align__(256) int    g_degi[MAX_NODES];
__device__ __align__(256) int    g_rtmp[MAX_NODES];
__device__ __align__(256) int    g_row_ptr[MAX_NODES + 1];
__device__ __align__(256) int    g_cursor[MAX_NODES];
__device__ __align__(256) int    g_csr_src[MAX_EDGES];
__device__ __align__(256) int    g_bsums[(MAX_NODES + SCAN_BLK - 1) / SCAN_BLK + 1];
__device__ int g_i64;   // 1 if edge_index is int64, 0 if int32

// ---------------------------------------------------------------------------
// Edge dtype detection (1 warp): int64 values < 1e5 have all-zero high words.
// ---------------------------------------------------------------------------
__global__ void detect_dtype_kernel(const int* __restrict__ ei32, int n_elem) {
    int lim = n_elem < 2048 ? n_elem : 2048;
    int acc = 0;
    for (int i = 1 + 2 * threadIdx.x; i < lim; i += 64) acc |= ei32[i];
    acc = __reduce_or_sync(0xffffffffu, acc);
    if (threadIdx.x == 0) g_i64 = (acc == 0) ? 1 : 0;
}

__device__ __forceinline__ int edge_val(const int* __restrict__ ei32, size_t elem, int sh) {
    return ei32[elem << sh];
}

// ---------------------------------------------------------------------------
// CSR build: degree histogram -> exclusive scan -> cursor fill
// ---------------------------------------------------------------------------
__global__ void count_deg_kernel(const int* __restrict__ ei32, int E, int M) {
    int e = blockIdx.x * blockDim.x + threadIdx.x;
    if (e < E) {
        int sh = g_i64;
        int d = edge_val(ei32, (size_t)E + e, sh);
        if ((unsigned)d < (unsigned)M) atomicAdd(&g_degi[d], 1);
    }
}

__global__ void dinv_kernel(int M) {
    int i = blockIdx.x * blockDim.x + threadIdx.x;
    if (i < M) g_dinv[i] = rsqrtf((float)g_degi[i] + 1.0f);  // +1 self loop
}

__global__ void scan1_kernel(int M) {
    __shared__ int sm[SCAN_BLK];
    int i = blockIdx.x * SCAN_BLK + threadIdx.x;
    int v = (i < M) ? g_degi[i] : 0;
    sm[threadIdx.x] = v;
    __syncthreads();
    for (int off = 1; off < SCAN_BLK; off <<= 1) {
        int t = (threadIdx.x >= off) ? sm[threadIdx.x - off] : 0;
        __syncthreads();
        sm[threadIdx.x] += t;
        __syncthreads();
    }
    if (i < M) g_rtmp[i] = sm[threadIdx.x] - v;          // exclusive within block
    if (threadIdx.x == SCAN_BLK - 1) g_bsums[blockIdx.x] = sm[SCAN_BLK - 1];
}

__global__ void scan2_kernel(int nb) {       // nb <= 128: one-block Hillis-Steele
    __shared__ int sm[128];
    int t = threadIdx.x;
    int v = (t < nb) ? g_bsums[t] : 0;
    sm[t] = v;
    __syncthreads();
    for (int off = 1; off < 128; off <<= 1) {
        int u = (t >= off) ? sm[t - off] : 0;
        __syncthreads();
        sm[t] += u;
        __syncthreads();
    }
    if (t < nb) g_bsums[t] = sm[t] - v;      // exclusive
}

__global__ void scan3_kernel(int M) {
    int i = blockIdx.x * blockDim.x + threadIdx.x;
    if (i < M) {
        int rp = g_rtmp[i] + g_bsums[i / SCAN_BLK];
        g_row_ptr[i] = rp;
        g_cursor[i]  = rp;
        if (i == M - 1) g_row_ptr[M] = rp + g_degi[i];
    }
}

__global__ void fill_csr_kernel(const int* __restrict__ ei32, int E, int M) {
    int e = blockIdx.x * blockDim.x + threadIdx.x;
    if (e < E) {
        int sh = g_i64;
        int s = edge_val(ei32, (size_t)e, sh);
        int d = edge_val(ei32, (size_t)E + e, sh);
        if ((unsigned)s < (unsigned)M && (unsigned)d < (unsigned)M) {
            int pos = atomicAdd(&g_cursor[d], 1);
            g_csr_src[pos] = s;
        }
    }
}

// ---------------------------------------------------------------------------
// fma.rn.f32x2 helper (even/odd-K packed partial sums)
// ---------------------------------------------------------------------------
__device__ __forceinline__ void fma2(u64& d, u64 a, u64 b) {
    asm("fma.rn.f32x2 %0, %1, %2, %0;" : "+l"(d) : "l"(a), "l"(b));
}

// ---------------------------------------------------------------------------
// GEMM: H[M,NC] = X[M,128] @ W[128,NC], fp32 compute (packed f32x2),
// epilogue converts to fp16 feature storage.
// ---------------------------------------------------------------------------
template <int NC>
__global__ void __launch_bounds__(256) gemm_kernel(
        const float* __restrict__ X, const float* __restrict__ W,
        __half* __restrict__ H, int M) {
    constexpr int WSTRIDE = 130;
    extern __shared__ float sh[];
    float* shWt = sh;                      // NC * WSTRIDE floats (transposed W)
    float* shX  = sh + NC * WSTRIDE;       // ROWS * 128 floats
    constexpr int ROWS = (NC == 128) ? 64 : 128;

    const int tid = threadIdx.x;
    const int rowBase = blockIdx.x * ROWS;

    for (int i = tid; i < 128 * NC; i += 256) {
        int k = i / NC, c = i % NC;
        shWt[c * WSTRIDE + k] = W[i];
    }
    for (int i = tid; i < ROWS * 32; i += 256) {
        int r = i >> 5;
        int gr = rowBase + r;
        float4 v = make_float4(0.f, 0.f, 0.f, 0.f);
        if (gr < M) v = ((const float4*)X)[(size_t)gr * 32 + (i & 31)];
        ((float4*)shX)[i] = v;
    }
    __syncthreads();

    const int warp = tid >> 5, lane = tid & 31;
    constexpr int CGRP = (NC == 128) ? 32 : 16;
    const int lc  = lane % CGRP;
    const int grp = lane / CGRP;
    constexpr int RPW = ROWS / 8;
    const int r0 = warp * RPW + grp * 8;

    u64 acc[8][4];
    #pragma unroll
    for (int r = 0; r < 8; ++r)
        #pragma unroll
        for (int j = 0; j < 4; ++j) acc[r][j] = 0ULL;

    const float* wbase = &shWt[lc * WSTRIDE];

    #pragma unroll 4
    for (int k2 = 0; k2 < 64; ++k2) {
        u64 w2[4];
        #pragma unroll
        for (int j = 0; j < 4; ++j)
            w2[j] = *(const u64*)&wbase[j * (CGRP * WSTRIDE) + 2 * k2];
        #pragma unroll
        for (int r = 0; r < 8; ++r) {
            u64 x2 = *(const u64*)&shX[(r0 + r) * 128 + 2 * k2];
            fma2(acc[r][0], x2, w2[0]);
            fma2(acc[r][1], x2, w2[1]);
            fma2(acc[r][2], x2, w2[2]);
            fma2(acc[r][3], x2, w2[3]);
        }
    }

    #pragma unroll
    for (int r = 0; r < 8; ++r) {
        int gr = rowBase + r0 + r;
        if (gr < M) {
            #pragma unroll
            for (int j = 0; j < 4; ++j) {
                u64 a = acc[r][j];
                float lo = __uint_as_float((unsigned)(a & 0xffffffffULL));
                float hi = __uint_as_float((unsigned)(a >> 32));
                H[(size_t)gr * NC + lc + CGRP * j] = __float2half(lo + hi);
            }
        }
    }
}

// ---------------------------------------------------------------------------
// Gather (CSR), fp16 features, fp32 accumulation:
//   out[d] = [relu]( dinv[d]*(h[d]*dinv[d] + sum_s h[s]*dinv[s]) + b )
// ---------------------------------------------------------------------------
__device__ __forceinline__ void h4_to_f4(uint2 u, float& a, float& b, float& c, float& d) {
    __half2 p0 = *reinterpret_cast<__half2*>(&u.x);
    __half2 p1 = *reinterpret_cast<__half2*>(&u.y);
    float2 f0 = __half22float2(p0);
    float2 f1 = __half22float2(p1);
    a = f0.x; b = f0.y; c = f1.x; d = f1.y;
}

template <bool RELU>
__global__ void gather128_kernel(const __half* __restrict__ Hs, const float* __restrict__ b,
                                 float* __restrict__ out, int M) {
    int row = (blockIdx.x * blockDim.x + threadIdx.x) >> 5;
    int lane = threadIdx.x & 31;
    if (row >= M) return;
    int p0 = __ldg(&g_row_ptr[row]);
    int p1 = __ldg(&g_row_ptr[row + 1]);
    float di = __ldg(&g_dinv[row]);
    float4 acc;
    {
        uint2 u = __ldg((const uint2*)&Hs[(size_t)row * 128 + lane * 4]);  // self loop
        h4_to_f4(u, acc.x, acc.y, acc.z, acc.w);
        acc.x *= di; acc.y *= di; acc.z *= di; acc.w *= di;
    }
    for (int base = p0; base < p1; base += 32) {
        int pl = base + lane;
        int s_l = 0; float dl = 0.f;
        if (pl < p1) { s_l = __ldg(&g_csr_src[pl]); dl = __ldg(&g_dinv[s_l]); }
        int n = min(32, p1 - base);
        int k = 0;
        for (; k + 4 <= n; k += 4) {
            int s0 = __shfl_sync(0xffffffffu, s_l, k);
            int s1 = __shfl_sync(0xffffffffu, s_l, k + 1);
            int s2 = __shfl_sync(0xffffffffu, s_l, k + 2);
            int s3 = __shfl_sync(0xffffffffu, s_l, k + 3);
            float d0 = __shfl_sync(0xffffffffu, dl, k);
            float d1 = __shfl_sync(0xffffffffu, dl, k + 1);
            float d2 = __shfl_sync(0xffffffffu, dl, k + 2);
            float d3 = __shfl_sync(0xffffffffu, dl, k + 3);
            uint2 u0 = __ldg((const uint2*)&Hs[(size_t)s0 * 128 + lane * 4]);
            uint2 u1 = __ldg((const uint2*)&Hs[(size_t)s1 * 128 + lane * 4]);
            uint2 u2 = __ldg((const uint2*)&Hs[(size_t)s2 * 128 + lane * 4]);
            uint2 u3 = __ldg((const uint2*)&Hs[(size_t)s3 * 128 + lane * 4]);
            float ax, ay, az, aw;
            h4_to_f4(u0, ax, ay, az, aw);
            acc.x += ax * d0; acc.y += ay * d0; acc.z += az * d0; acc.w += aw * d0;
            h4_to_f4(u1, ax, ay, az, aw);
            acc.x += ax * d1; acc.y += ay * d1; acc.z += az * d1; acc.w += aw * d1;
            h4_to_f4(u2, ax, ay, az, aw);
            acc.x += ax * d2; acc.y += ay * d2; acc.z += az * d2; acc.w += aw * d2;
            h4_to_f4(u3, ax, ay, az, aw);
            acc.x += ax * d3; acc.y += ay * d3; acc.z += az * d3; acc.w += aw * d3;
        }
        for (; k < n; ++k) {
            int s = __shfl_sync(0xffffffffu, s_l, k);
            float d = __shfl_sync(0xffffffffu, dl, k);
            uint2 u = __ldg((const uint2*)&Hs[(size_t)s * 128 + lane * 4]);
            float ax, ay, az, aw;
            h4_to_f4(u, ax, ay, az, aw);
            acc.x += ax * d; acc.y += ay * d; acc.z += az * d; acc.w += aw * d;
        }
    }
    float4 bv = __ldg((const float4*)&b[lane * 4]);
    float4 o;
    o.x = acc.x * di + bv.x;
    o.y = acc.y * di + bv.y;
    o.z = acc.z * di + bv.z;
    o.w = acc.w * di + bv.w;
    if (RELU) {
        o.x = fmaxf(o.x, 0.f); o.y = fmaxf(o.y, 0.f);
        o.z = fmaxf(o.z, 0.f); o.w = fmaxf(o.w, 0.f);
    }
    *(float4*)&out[(size_t)row * 128 + lane * 4] = o;
}

__global__ void gather64_kernel(const __half* __restrict__ Hs, const float* __restrict__ b,
                                float* __restrict__ out, int M) {
    int row = (blockIdx.x * blockDim.x + threadIdx.x) >> 5;
    int lane = threadIdx.x & 31;
    if (row >= M) return;
    int p0 = __ldg(&g_row_ptr[row]);
    int p1 = __ldg(&g_row_ptr[row + 1]);
    float di = __ldg(&g_dinv[row]);
    float2 acc;
    {
        unsigned u = __ldg((const unsigned*)&Hs[(size_t)row * 64 + lane * 2]); // self loop
        float2 f = __half22float2(*reinterpret_cast<__half2*>(&u));
        acc.x = f.x * di; acc.y = f.y * di;
    }
    for (int base = p0; base < p1; base += 32) {
        int pl = base + lane;
        int s_l = 0; float dl = 0.f;
        if (pl < p1) { s_l = __ldg(&g_csr_src[pl]); dl = __ldg(&g_dinv[s_l]); }
        int n = min(32, p1 - base);
        int k = 0;
        for (; k + 4 <= n; k += 4) {
            int s0 = __shfl_sync(0xffffffffu, s_l, k);
            int s1 = __shfl_sync(0xffffffffu, s_l, k + 1);
            int s2 = __shfl_sync(0xffffffffu, s_l, k + 2);
            int s3 = __shfl_sync(0xffffffffu, s_l, k + 3);
            float d0 = __shfl_sync(0xffffffffu, dl, k);
            float d1 = __shfl_sync(0xffffffffu, dl, k + 1);
            float d2 = __shfl_sync(0xffffffffu, dl, k + 2);
            float d3 = __shfl_sync(0xffffffffu, dl, k + 3);
            unsigned u0 = __ldg((const unsigned*)&Hs[(size_t)s0 * 64 + lane * 2]);
            unsigned u1 = __ldg((const unsigned*)&Hs[(size_t)s1 * 64 + lane * 2]);
            unsigned u2 = __ldg((const unsigned*)&Hs[(size_t)s2 * 64 + lane * 2]);
            unsigned u3 = __ldg((const unsigned*)&Hs[(size_t)s3 * 64 + lane * 2]);
            float2 f0 = __half22float2(*reinterpret_cast<__half2*>(&u0));
            float2 f1 = __half22float2(*reinterpret_cast<__half2*>(&u1));
            float2 f2 = __half22float2(*reinterpret_cast<__half2*>(&u2));
            float2 f3 = __half22float2(*reinterpret_cast<__half2*>(&u3));
            acc.x += f0.x * d0 + f1.x * d1 + f2.x * d2 + f3.x * d3;
            acc.y += f0.y * d0 + f1.y * d1 + f2.y * d2 + f3.y * d3;
        }
        for (; k < n; ++k) {
            int s = __shfl_sync(0xffffffffu, s_l, k);
            float d = __shfl_sync(0xffffffffu, dl, k);
            unsigned u = __ldg((const unsigned*)&Hs[(size_t)s * 64 + lane * 2]);
            float2 f = __half22float2(*reinterpret_cast<__half2*>(&u));
            acc.x += f.x * d; acc.y += f.y * d;
        }
    }
    float2 bv = __ldg((const float2*)&b[lane * 2]);
    float2 o;
    o.x = acc.x * di + bv.x;
    o.y = acc.y * di + bv.y;
    *(float2*)&out[(size_t)row * 64 + lane * 2] = o;
}

// ---------------------------------------------------------------------------
// Launch — R9 schedule: CSR chain on side stream overlapped with gemm128,
// then serial gather128 -> gemm64 -> gather64 on the main stream.
// ---------------------------------------------------------------------------
extern "C" void kernel_launch(void* const* d_in, const int* in_sizes, int n_in,
                              void* d_out, int out_size) {
    int idxs[8];
    for (int i = 0; i < n_in; ++i) idxs[i] = i;
    for (int i = 0; i < n_in; ++i)
        for (int j = i + 1; j < n_in; ++j)
            if (in_sizes[idxs[j]] > in_sizes[idxs[i]]) { int t = idxs[i]; idxs[i] = idxs[j]; idxs[j] = t; }

    const float* x    = (const float*)d_in[idxs[0]];
    const int*   ei32 = (const int*)  d_in[idxs[1]];
    const float* W1   = (const float*)d_in[idxs[2]];
    const float* W2   = (const float*)d_in[idxs[3]];
    const float* b1   = (const float*)d_in[idxs[4]];
    const float* b2   = (const float*)d_in[idxs[5]];
    const int x_elems = in_sizes[idxs[0]];
    const int e_elems = in_sizes[idxs[1]];

    const int M = x_elems / 128;   // 100000
    const int E = e_elems / 2;     // 1600000
    const int NB = (M + SCAN_BLK - 1) / SCAN_BLK;

    void *p_degi, *p_h1, *p_y, *p_h2;
    cudaGetSymbolAddress(&p_degi, g_degi);
    cudaGetSymbolAddress(&p_h1,   g_h1h);
    cudaGetSymbolAddress(&p_y,    g_y);
    cudaGetSymbolAddress(&p_h2,   g_h2h);

    const int SMEM128 = (128 * 130 + 64 * 128) * 4;   // 99,328 B
    const int SMEM64  = (64 * 130 + 128 * 128) * 4;   // 98,816 B
    cudaFuncSetAttribute(gemm_kernel<128>, cudaFuncAttributeMaxDynamicSharedMemorySize, SMEM128);
    cudaFuncSetAttribute(gemm_kernel<64>,  cudaFuncAttributeMaxDynamicSharedMemorySize, SMEM64);

    static cudaStream_t sB = nullptr;
    static cudaEvent_t evF = nullptr, evJ = nullptr;
    if (!sB) {
        cudaStreamCreateWithFlags(&sB, cudaStreamNonBlocking);
        cudaEventCreateWithFlags(&evF, cudaEventDisableTiming);
        cudaEventCreateWithFlags(&evJ, cudaEventDisableTiming);
    }

    // Fork: CSR chain on side stream sB (overlaps gemm128).
    cudaEventRecord(evF, 0);
    cudaStreamWaitEvent(sB, evF, 0);
    detect_dtype_kernel<<<1, 32, 0, sB>>>(ei32, e_elems);
    cudaMemsetAsync(p_degi, 0, (size_t)M * sizeof(int), sB);
    count_deg_kernel<<<(E + 255) / 256, 256, 0, sB>>>(ei32, E, M);
    dinv_kernel<<<(M + 255) / 256, 256, 0, sB>>>(M);
    scan1_kernel<<<NB, SCAN_BLK, 0, sB>>>(M);
    scan2_kernel<<<1, 128, 0, sB>>>(NB);
    scan3_kernel<<<(M + 255) / 256, 256, 0, sB>>>(M);
    fill_csr_kernel<<<(E + 255) / 256, 256, 0, sB>>>(ei32, E, M);
    cudaEventRecord(evJ, sB);

    // Concurrent: layer-1 GEMM (depends only on x, W1).
    gemm_kernel<128><<<(M + 63) / 64, 256, SMEM128>>>(x, W1, (__half*)p_h1, M);

    // Join, then the serial dependent chain.
    cudaStreamWaitEvent(0, evJ, 0);
    gather128_kernel<true><<<(M * 32 + 255) / 256, 256>>>(
        (const __half*)p_h1, b1, (float*)p_y, M);
    gemm_kernel<64><<<(M + 127) / 128, 256, SMEM64>>>(
        (const float*)p_y, W2, (__half*)p_h2, M);
    gather64_kernel<<<(M * 32 + 255) / 256, 256>>>(
        (const __half*)p_h2, b2, (float*)d_out, M);
}

// round 14
// speedup vs baseline: 1.5563x; 1.0486x over previous
#include <cuda_runtime.h>
#include <cuda_fp16.h>
#include <cstdint>

#define MAX_NODES 100000
#define MAX_EDGES 1600000
#define SCAN_BLK 1024

typedef unsigned long long u64;

// Scratch (allocation-free device globals); 256B-aligned.
__device__ __align__(256) __half g_h1h[(size_t)MAX_NODES * 128]; // h1 = X@W1 (fp16)
__device__ __align__(256) float  g_y[(size_t)MAX_NODES * 128];   // layer-1 output (fp32)
__device__ __align__(256) __half g_h2h[(size_t)MAX_NODES * 64];  // h2 = y@W2 (fp16)
__device__ __align__(256) float  g_dinv[MAX_NODES];
__device__ __align__(256) int    g_degi[MAX_NODES];
__device__ __align__(256) int    g_rtmp[MAX_NODES];
__device__ __align__(256) int    g_row_ptr[MAX_NODES + 1];
__device__ __align__(256) int    g_cursor[MAX_NODES];
__device__ __align__(256) int    g_csr_src[MAX_EDGES];
__device__ __align__(256) int    g_bsums[(MAX_NODES + SCAN_BLK - 1) / SCAN_BLK + 1];
__device__ int g_i64;   // 1 if edge_index is int64, 0 if int32

// ---------------------------------------------------------------------------
// Edge dtype detection (1 warp): int64 values < 1e5 have all-zero high words.
// ---------------------------------------------------------------------------
__global__ void detect_dtype_kernel(const int* __restrict__ ei32, int n_elem) {
    int lim = n_elem < 2048 ? n_elem : 2048;
    int acc = 0;
    for (int i = 1 + 2 * threadIdx.x; i < lim; i += 64) acc |= ei32[i];
    acc = __reduce_or_sync(0xffffffffu, acc);
    if (threadIdx.x == 0) g_i64 = (acc == 0) ? 1 : 0;
}

__device__ __forceinline__ int edge_val(const int* __restrict__ ei32, size_t elem, int sh) {
    return ei32[elem << sh];
}

// ---------------------------------------------------------------------------
// CSR build: degree histogram -> exclusive scan -> cursor fill
// ---------------------------------------------------------------------------
__global__ void count_deg_kernel(const int* __restrict__ ei32, int E, int M) {
    int e = blockIdx.x * blockDim.x + threadIdx.x;
    if (e < E) {
        int sh = g_i64;
        int d = edge_val(ei32, (size_t)E + e, sh);
        if ((unsigned)d < (unsigned)M) atomicAdd(&g_degi[d], 1);
    }
}

__global__ void dinv_kernel(int M) {
    int i = blockIdx.x * blockDim.x + threadIdx.x;
    if (i < M) g_dinv[i] = rsqrtf((float)g_degi[i] + 1.0f);  // +1 self loop
}

__global__ void scan1_kernel(int M) {
    __shared__ int sm[SCAN_BLK];
    int i = blockIdx.x * SCAN_BLK + threadIdx.x;
    int v = (i < M) ? g_degi[i] : 0;
    sm[threadIdx.x] = v;
    __syncthreads();
    for (int off = 1; off < SCAN_BLK; off <<= 1) {
        int t = (threadIdx.x >= off) ? sm[threadIdx.x - off] : 0;
        __syncthreads();
        sm[threadIdx.x] += t;
        __syncthreads();
    }
    if (i < M) g_rtmp[i] = sm[threadIdx.x] - v;          // exclusive within block
    if (threadIdx.x == SCAN_BLK - 1) g_bsums[blockIdx.x] = sm[SCAN_BLK - 1];
}

__global__ void scan2_kernel(int nb) {       // nb <= 128: one-block Hillis-Steele
    __shared__ int sm[128];
    int t = threadIdx.x;
    int v = (t < nb) ? g_bsums[t] : 0;
    sm[t] = v;
    __syncthreads();
    for (int off = 1; off < 128; off <<= 1) {
        int u = (t >= off) ? sm[t - off] : 0;
        __syncthreads();
        sm[t] += u;
        __syncthreads();
    }
    if (t < nb) g_bsums[t] = sm[t] - v;      // exclusive
}

__global__ void scan3_kernel(int M) {
    int i = blockIdx.x * blockDim.x + threadIdx.x;
    if (i < M) {
        int rp = g_rtmp[i] + g_bsums[i / SCAN_BLK];
        g_row_ptr[i] = rp;
        g_cursor[i]  = rp;
        if (i == M - 1) g_row_ptr[M] = rp + g_degi[i];
    }
}

__global__ void fill_csr_kernel(const int* __restrict__ ei32, int E, int M) {
    int e = blockIdx.x * blockDim.x + threadIdx.x;
    if (e < E) {
        int sh = g_i64;
        int s = edge_val(ei32, (size_t)e, sh);
        int d = edge_val(ei32, (size_t)E + e, sh);
        if ((unsigned)s < (unsigned)M && (unsigned)d < (unsigned)M) {
            int pos = atomicAdd(&g_cursor[d], 1);
            g_csr_src[pos] = s;
        }
    }
}

// ---------------------------------------------------------------------------
// fma.rn.f32x2 helper (even/odd-K packed partial sums)
// ---------------------------------------------------------------------------
__device__ __forceinline__ void fma2(u64& d, u64 a, u64 b) {
    asm("fma.rn.f32x2 %0, %1, %2, %0;" : "+l"(d) : "l"(a), "l"(b));
}

// ---------------------------------------------------------------------------
// GEMM: H[M,NC] = X[M,128] @ W[128,NC], fp32 compute (packed f32x2),
// epilogue converts to fp16 feature storage.
// ---------------------------------------------------------------------------
template <int NC>
__global__ void __launch_bounds__(256) gemm_kernel(
        const float* __restrict__ X, const float* __restrict__ W,
        __half* __restrict__ H, int M) {
    constexpr int WSTRIDE = 130;
    extern __shared__ float sh[];
    float* shWt = sh;                      // NC * WSTRIDE floats (transposed W)
    float* shX  = sh + NC * WSTRIDE;       // ROWS * 128 floats
    constexpr int ROWS = (NC == 128) ? 64 : 128;

    const int tid = threadIdx.x;
    const int rowBase = blockIdx.x * ROWS;

    for (int i = tid; i < 128 * NC; i += 256) {
        int k = i / NC, c = i % NC;
        shWt[c * WSTRIDE + k] = W[i];
    }
    for (int i = tid; i < ROWS * 32; i += 256) {
        int r = i >> 5;
        int gr = rowBase + r;
        float4 v = make_float4(0.f, 0.f, 0.f, 0.f);
        if (gr < M) v = ((const float4*)X)[(size_t)gr * 32 + (i & 31)];
        ((float4*)shX)[i] = v;
    }
    __syncthreads();

    const int warp = tid >> 5, lane = tid & 31;
    constexpr int CGRP = (NC == 128) ? 32 : 16;
    const int lc  = lane % CGRP;
    const int grp = lane / CGRP;
    constexpr int RPW = ROWS / 8;
    const int r0 = warp * RPW + grp * 8;

    u64 acc[8][4];
    #pragma unroll
    for (int r = 0; r < 8; ++r)
        #pragma unroll
        for (int j = 0; j < 4; ++j) acc[r][j] = 0ULL;

    const float* wbase = &shWt[lc * WSTRIDE];

    #pragma unroll 4
    for (int k2 = 0; k2 < 64; ++k2) {
        u64 w2[4];
        #pragma unroll
        for (int j = 0; j < 4; ++j)
            w2[j] = *(const u64*)&wbase[j * (CGRP * WSTRIDE) + 2 * k2];
        #pragma unroll
        for (int r = 0; r < 8; ++r) {
            u64 x2 = *(const u64*)&shX[(r0 + r) * 128 + 2 * k2];
            fma2(acc[r][0], x2, w2[0]);
            fma2(acc[r][1], x2, w2[1]);
            fma2(acc[r][2], x2, w2[2]);
            fma2(acc[r][3], x2, w2[3]);
        }
    }

    #pragma unroll
    for (int r = 0; r < 8; ++r) {
        int gr = rowBase + r0 + r;
        if (gr < M) {
            #pragma unroll
            for (int j = 0; j < 4; ++j) {
                u64 a = acc[r][j];
                float lo = __uint_as_float((unsigned)(a & 0xffffffffULL));
                float hi = __uint_as_float((unsigned)(a >> 32));
                H[(size_t)gr * NC + lc + CGRP * j] = __float2half(lo + hi);
            }
        }
    }
}

// ---------------------------------------------------------------------------
// Gather (CSR), fp16 features, fp32 accumulation, 8-deep MLP:
//   out[d] = [relu]( dinv[d]*(h[d]*dinv[d] + sum_s h[s]*dinv[s]) + b )
// ---------------------------------------------------------------------------
__device__ __forceinline__ void h4_to_f4(uint2 u, float& a, float& b, float& c, float& d) {
    __half2 p0 = *reinterpret_cast<__half2*>(&u.x);
    __half2 p1 = *reinterpret_cast<__half2*>(&u.y);
    float2 f0 = __half22float2(p0);
    float2 f1 = __half22float2(p1);
    a = f0.x; b = f0.y; c = f1.x; d = f1.y;
}

template <bool RELU>
__global__ void gather128_kernel(const __half* __restrict__ Hs, const float* __restrict__ b,
                                 float* __restrict__ out, int M) {
    int row = (blockIdx.x * blockDim.x + threadIdx.x) >> 5;
    int lane = threadIdx.x & 31;
    if (row >= M) return;
    int p0 = __ldg(&g_row_ptr[row]);
    int p1 = __ldg(&g_row_ptr[row + 1]);
    float di = __ldg(&g_dinv[row]);
    float4 acc;
    {
        uint2 u = __ldg((const uint2*)&Hs[(size_t)row * 128 + lane * 4]);  // self loop
        h4_to_f4(u, acc.x, acc.y, acc.z, acc.w);
        acc.x *= di; acc.y *= di; acc.z *= di; acc.w *= di;
    }
    for (int base = p0; base < p1; base += 32) {
        int pl = base + lane;
        int s_l = 0; float dl = 0.f;
        if (pl < p1) { s_l = __ldg(&g_csr_src[pl]); dl = __ldg(&g_dinv[s_l]); }
        int n = min(32, p1 - base);
        int k = 0;
        for (; k + 8 <= n; k += 8) {          // 8 outstanding row-loads (MLP=8)
            int   si[8]; float dd[8]; uint2 uu[8];
            #pragma unroll
            for (int q = 0; q < 8; ++q) {
                si[q] = __shfl_sync(0xffffffffu, s_l, k + q);
                dd[q] = __shfl_sync(0xffffffffu, dl, k + q);
            }
            #pragma unroll
            for (int q = 0; q < 8; ++q)
                uu[q] = __ldg((const uint2*)&Hs[(size_t)si[q] * 128 + lane * 4]);
            #pragma unroll
            for (int q = 0; q < 8; ++q) {
                float ax, ay, az, aw;
                h4_to_f4(uu[q], ax, ay, az, aw);
                acc.x += ax * dd[q]; acc.y += ay * dd[q];
                acc.z += az * dd[q]; acc.w += aw * dd[q];
            }
        }
        for (; k + 4 <= n; k += 4) {
            int   si[4]; float dd[4]; uint2 uu[4];
            #pragma unroll
            for (int q = 0; q < 4; ++q) {
                si[q] = __shfl_sync(0xffffffffu, s_l, k + q);
                dd[q] = __shfl_sync(0xffffffffu, dl, k + q);
            }
            #pragma unroll
            for (int q = 0; q < 4; ++q)
                uu[q] = __ldg((const uint2*)&Hs[(size_t)si[q] * 128 + lane * 4]);
            #pragma unroll
            for (int q = 0; q < 4; ++q) {
                float ax, ay, az, aw;
                h4_to_f4(uu[q], ax, ay, az, aw);
                acc.x += ax * dd[q]; acc.y += ay * dd[q];
                acc.z += az * dd[q]; acc.w += aw * dd[q];
            }
        }
        for (; k < n; ++k) {
            int s = __shfl_sync(0xffffffffu, s_l, k);
            float d = __shfl_sync(0xffffffffu, dl, k);
            uint2 u = __ldg((const uint2*)&Hs[(size_t)s * 128 + lane * 4]);
            float ax, ay, az, aw;
            h4_to_f4(u, ax, ay, az, aw);
            acc.x += ax * d; acc.y += ay * d; acc.z += az * d; acc.w += aw * d;
        }
    }
    float4 bv = __ldg((const float4*)&b[lane * 4]);
    float4 o;
    o.x = acc.x * di + bv.x;
    o.y = acc.y * di + bv.y;
    o.z = acc.z * di + bv.z;
    o.w = acc.w * di + bv.w;
    if (RELU) {
        o.x = fmaxf(o.x, 0.f); o.y = fmaxf(o.y, 0.f);
        o.z = fmaxf(o.z, 0.f); o.w = fmaxf(o.w, 0.f);
    }
    *(float4*)&out[(size_t)row * 128 + lane * 4] = o;
}

__global__ void gather64_kernel(const __half* __restrict__ Hs, const float* __restrict__ b,
                                float* __restrict__ out, int M) {
    int row = (blockIdx.x * blockDim.x + threadIdx.x) >> 5;
    int lane = threadIdx.x & 31;
    if (row >= M) return;
    int p0 = __ldg(&g_row_ptr[row]);
    int p1 = __ldg(&g_row_ptr[row + 1]);
    float di = __ldg(&g_dinv[row]);
    float2 acc;
    {
        unsigned u = __ldg((const unsigned*)&Hs[(size_t)row * 64 + lane * 2]); // self loop
        float2 f = __half22float2(*reinterpret_cast<__half2*>(&u));
        acc.x = f.x * di; acc.y = f.y * di;
    }
    for (int base = p0; base < p1; base += 32) {
        int pl = base + lane;
        int s_l = 0; float dl = 0.f;
        if (pl < p1) { s_l = __ldg(&g_csr_src[pl]); dl = __ldg(&g_dinv[s_l]); }
        int n = min(32, p1 - base);
        int k = 0;
        for (; k + 8 <= n; k += 8) {          // MLP=8
            int si[8]; float dd[8]; unsigned uu[8];
            #pragma unroll
            for (int q = 0; q < 8; ++q) {
                si[q] = __shfl_sync(0xffffffffu, s_l, k + q);
                dd[q] = __shfl_sync(0xffffffffu, dl, k + q);
            }
            #pragma unroll
            for (int q = 0; q < 8; ++q)
                uu[q] = __ldg((const unsigned*)&Hs[(size_t)si[q] * 64 + lane * 2]);
            #pragma unroll
            for (int q = 0; q < 8; ++q) {
                float2 f = __half22float2(*reinterpret_cast<__half2*>(&uu[q]));
                acc.x += f.x * dd[q]; acc.y += f.y * dd[q];
            }
        }
        for (; k + 4 <= n; k += 4) {
            int si[4]; float dd[4]; unsigned uu[4];
            #pragma unroll
            for (int q = 0; q < 4; ++q) {
                si[q] = __shfl_sync(0xffffffffu, s_l, k + q);
                dd[q] = __shfl_sync(0xffffffffu, dl, k + q);
            }
            #pragma unroll
            for (int q = 0; q < 4; ++q)
                uu[q] = __ldg((const unsigned*)&Hs[(size_t)si[q] * 64 + lane * 2]);
            #pragma unroll
            for (int q = 0; q < 4; ++q) {
                float2 f = __half22float2(*reinterpret_cast<__half2*>(&uu[q]));
                acc.x += f.x * dd[q]; acc.y += f.y * dd[q];
            }
        }
        for (; k < n; ++k) {
            int s = __shfl_sync(0xffffffffu, s_l, k);
            float d = __shfl_sync(0xffffffffu, dl, k);
            unsigned u = __ldg((const unsigned*)&Hs[(size_t)s * 64 + lane * 2]);
            float2 f = __half22float2(*reinterpret_cast<__half2*>(&u));
            acc.x += f.x * d; acc.y += f.y * d;
        }
    }
    float2 bv = __ldg((const float2*)&b[lane * 2]);
    float2 o;
    o.x = acc.x * di + bv.x;
    o.y = acc.y * di + bv.y;
    *(float2*)&out[(size_t)row * 64 + lane * 2] = o;
}

// ---------------------------------------------------------------------------
// Launch — R9 schedule: CSR chain on side stream overlapped with gemm128,
// then serial gather128 -> gemm64 -> gather64 on the main stream.
// ---------------------------------------------------------------------------
extern "C" void kernel_launch(void* const* d_in, const int* in_sizes, int n_in,
                              void* d_out, int out_size) {
    int idxs[8];
    for (int i = 0; i < n_in; ++i) idxs[i] = i;
    for (int i = 0; i < n_in; ++i)
        for (int j = i + 1; j < n_in; ++j)
            if (in_sizes[idxs[j]] > in_sizes[idxs[i]]) { int t = idxs[i]; idxs[i] = idxs[j]; idxs[j] = t; }

    const float* x    = (const float*)d_in[idxs[0]];
    const int*   ei32 = (const int*)  d_in[idxs[1]];
    const float* W1   = (const float*)d_in[idxs[2]];
    const float* W2   = (const float*)d_in[idxs[3]];
    const float* b1   = (const float*)d_in[idxs[4]];
    const float* b2   = (const float*)d_in[idxs[5]];
    const int x_elems = in_sizes[idxs[0]];
    const int e_elems = in_sizes[idxs[1]];

    const int M = x_elems / 128;   // 100000
    const int E = e_elems / 2;     // 1600000
    const int NB = (M + SCAN_BLK - 1) / SCAN_BLK;

    void *p_degi, *p_h1, *p_y, *p_h2;
    cudaGetSymbolAddress(&p_degi, g_degi);
    cudaGetSymbolAddress(&p_h1,   g_h1h);
    cudaGetSymbolAddress(&p_y,    g_y);
    cudaGetSymbolAddress(&p_h2,   g_h2h);

    const int SMEM128 = (128 * 130 + 64 * 128) * 4;   // 99,328 B
    const int SMEM64  = (64 * 130 + 128 * 128) * 4;   // 98,816 B
    cudaFuncSetAttribute(gemm_kernel<128>, cudaFuncAttributeMaxDynamicSharedMemorySize, SMEM128);
    cudaFuncSetAttribute(gemm_kernel<64>,  cudaFuncAttributeMaxDynamicSharedMemorySize, SMEM64);

    static cudaStream_t sB = nullptr;
    static cudaEvent_t evF = nullptr, evJ = nullptr;
    if (!sB) {
        cudaStreamCreateWithFlags(&sB, cudaStreamNonBlocking);
        cudaEventCreateWithFlags(&evF, cudaEventDisableTiming);
        cudaEventCreateWithFlags(&evJ, cudaEventDisableTiming);
    }

    // Fork: CSR chain on side stream sB (overlaps gemm128).
    cudaEventRecord(evF, 0);
    cudaStreamWaitEvent(sB, evF, 0);
    detect_dtype_kernel<<<1, 32, 0, sB>>>(ei32, e_elems);
    cudaMemsetAsync(p_degi, 0, (size_t)M * sizeof(int), sB);
    count_deg_kernel<<<(E + 255) / 256, 256, 0, sB>>>(ei32, E, M);
    dinv_kernel<<<(M + 255) / 256, 256, 0, sB>>>(M);
    scan1_kernel<<<NB, SCAN_BLK, 0, sB>>>(M);
    scan2_kernel<<<1, 128, 0, sB>>>(NB);
    scan3_kernel<<<(M + 255) / 256, 256, 0, sB>>>(M);
    fill_csr_kernel<<<(E + 255) / 256, 256, 0, sB>>>(ei32, E, M);
    cudaEventRecord(evJ, sB);

    // Concurrent: layer-1 GEMM (depends only on x, W1).
    gemm_kernel<128><<<(M + 63) / 64, 256, SMEM128>>>(x, W1, (__half*)p_h1, M);

    // Join, then the serial dependent chain.
    cudaStreamWaitEvent(0, evJ, 0);
    gather128_kernel<true><<<(M * 32 + 255) / 256, 256>>>(
        (const __half*)p_h1, b1, (float*)p_y, M);
    gemm_kernel<64><<<(M + 127) / 128, 256, SMEM64>>>(
        (const float*)p_y, W2, (__half*)p_h2, M);
    gather64_kernel<<<(M * 32 + 255) / 256, 256>>>(
        (const __half*)p_h2, b2, (float*)d_out, M);
}